// round 9
// baseline (speedup 1.0000x reference)
#include <cuda_runtime.h>
#include <cuda_bf16.h>
#include <cstdint>

#define N_NODES 50000
#define HIDDEN 128
#define N_REL 9
#define N_LAYERS 3
#define N_EDGES 600000
#define TILE_M 128
#define MAX_TILES 3600
#define NP (N_NODES * N_REL)          // 450000 (d,r) pairs
#define SCAN_CHUNK 4096
#define SCAN_NBLK 110                 // ceil(450000/4096)

// ---------------- device scratch (no allocations allowed) ----------------
__device__ float g_buf[2][N_NODES * HIDDEN];          // layer ping-pong fp32
__device__ __nv_bfloat16 g_inb[N_NODES * HIDDEN];     // bf16 layer input
__device__ __nv_bfloat16 g_agg[(size_t)NP * HIDDEN];  // aggregated rows (bf16)
__device__ char g_wbf[N_LAYERS * N_REL * 32768];      // pre-swizzled bf16 weights
__device__ int g_srcS[N_EDGES];                       // src sorted by (rel,dest)
__device__ int g_cnt[NP];                             // histogram [d*9+r]
__device__ unsigned long long g_scanv[NP];            // per-elem exclusive scan
__device__ unsigned long long g_bsum[SCAN_NBLK];      // block sums (-> exclusive)
__device__ int g_aggDst[NP];                          // agg row -> dest node
__device__ int g_aggStart[NP];                        // agg row -> first edge
__device__ int g_aggCnt[NP];                          // agg row -> edge count
__device__ int g_curE[NP];                            // edge-scatter cursors
__device__ int g_aggTotal;
__device__ int g_tileRel[MAX_TILES];
__device__ int g_tileStart[MAX_TILES];                // in agg-row units
__device__ int g_tileCnt[MAX_TILES];
__device__ int g_numTiles;

// ---------------- helpers ----------------
__device__ __forceinline__ uint32_t smem_u32(const void* p) {
    uint32_t a;
    asm("{ .reg .u64 t; cvta.to.shared.u64 t, %1; cvt.u32.u64 %0, t; }" : "=r"(a) : "l"(p));
    return a;
}

// 256-byte rows, XOR-swizzle 16B group index with (row & 7): conflict-free ldmatrix
__device__ __forceinline__ uint32_t swz(int row, int colByte) {
    return (uint32_t)(row * 256 + (colByte ^ ((row & 7) << 4)));
}

__device__ __forceinline__ uint4 cvt8(float4 x, float4 y, int relu) {
    if (relu) {
        x.x = fmaxf(x.x, 0.f); x.y = fmaxf(x.y, 0.f);
        x.z = fmaxf(x.z, 0.f); x.w = fmaxf(x.w, 0.f);
        y.x = fmaxf(y.x, 0.f); y.y = fmaxf(y.y, 0.f);
        y.z = fmaxf(y.z, 0.f); y.w = fmaxf(y.w, 0.f);
    }
    __nv_bfloat162 b0 = __floats2bfloat162_rn(x.x, x.y);
    __nv_bfloat162 b1 = __floats2bfloat162_rn(x.z, x.w);
    __nv_bfloat162 b2 = __floats2bfloat162_rn(y.x, y.y);
    __nv_bfloat162 b3 = __floats2bfloat162_rn(y.z, y.w);
    uint4 u;
    u.x = *(unsigned*)&b0; u.y = *(unsigned*)&b1;
    u.z = *(unsigned*)&b2; u.w = *(unsigned*)&b3;
    return u;
}

// ---------------- pre-pass kernels ----------------
__global__ void k_hist(const int* __restrict__ ei, const int* __restrict__ et) {
    int e = blockIdx.x * blockDim.x + threadIdx.x;
    if (e < N_EDGES) atomicAdd(&g_cnt[ei[e] * N_REL + et[e]], 1);
}

// scan phase 1: per-block exclusive scan of packed (count | nz<<32) over j=r*N+d
__global__ void __launch_bounds__(512) k_scan1() {
    __shared__ unsigned long long wsum[16];
    int tid = threadIdx.x, b = blockIdx.x;
    int base = b * SCAN_CHUNK + tid * 8;
    unsigned long long v[8], run = 0;
#pragma unroll
    for (int k = 0; k < 8; k++) {
        int j = base + k;
        unsigned long long x = 0;
        if (j < NP) {
            int r = j / N_NODES, d = j - r * N_NODES;
            int c = g_cnt[d * N_REL + r];
            x = (unsigned long long)c | ((unsigned long long)(c > 0) << 32);
        }
        v[k] = run; run += x;
    }
    int lid = tid & 31, wid = tid >> 5;
    unsigned long long ts = run;
#pragma unroll
    for (int o = 1; o < 32; o <<= 1) {
        unsigned long long y = __shfl_up_sync(0xffffffffu, ts, o);
        if (lid >= o) ts += y;
    }
    unsigned long long wexcl = ts - run;
    if (lid == 31) wsum[wid] = ts;
    __syncthreads();
    if (wid == 0) {
        unsigned long long w = (lid < 16) ? wsum[lid] : 0ull;
#pragma unroll
        for (int o = 1; o < 16; o <<= 1) {
            unsigned long long y = __shfl_up_sync(0xffffffffu, w, o);
            if (lid >= o) w += y;
        }
        if (lid < 16) wsum[lid] = w;   // inclusive warp-total scan
    }
    __syncthreads();
    unsigned long long bexcl = (wid == 0) ? 0ull : wsum[wid - 1];
    unsigned long long tbase = bexcl + wexcl;
#pragma unroll
    for (int k = 0; k < 8; k++) {
        int j = base + k;
        if (j < NP) g_scanv[j] = tbase + v[k];
    }
    if (tid == 0) g_bsum[b] = wsum[15];
}

// scan phase 2 (block sums -> exclusive) + per-relation agg bases + tile table
__global__ void k_scan2tiles() {
    __shared__ int relStart[N_REL + 1];
    __shared__ int toffs[N_REL + 1];
    int tid = threadIdx.x;
    if (tid == 0) {
        unsigned long long acc = 0;
        for (int i = 0; i < SCAN_NBLK; i++) {
            unsigned long long t = g_bsum[i];
            g_bsum[i] = acc;
            acc += t;
        }
        g_aggTotal = (int)(acc >> 32);
        relStart[N_REL] = (int)(acc >> 32);
    }
    __syncthreads();
    if (tid < N_REL) {
        int j = tid * N_NODES;
        unsigned long long f = g_scanv[j] + g_bsum[j / SCAN_CHUNK];
        relStart[tid] = (int)(f >> 32);
    }
    __syncthreads();
    if (tid == 0) {
        int to = 0;
        for (int r = 0; r < N_REL; r++) {
            toffs[r] = to;
            to += (relStart[r + 1] - relStart[r] + TILE_M - 1) / TILE_M;
        }
        toffs[N_REL] = to;
        g_numTiles = to;
    }
    __syncthreads();
    for (int r = 0; r < N_REL; r++) {
        int cr = relStart[r + 1] - relStart[r];
        int nt = (cr + TILE_M - 1) / TILE_M;
        for (int i = tid; i < nt; i += blockDim.x) {
            int t = toffs[r] + i;
            g_tileRel[t] = r;
            g_tileStart[t] = relStart[r] + i * TILE_M;
            g_tileCnt[t] = min(TILE_M, cr - i * TILE_M);
        }
    }
}

// scan phase 3: fill agg tables + edge cursors
__global__ void __launch_bounds__(512) k_scan3() {
    int tid = threadIdx.x, b = blockIdx.x;
    int base = b * SCAN_CHUNK + tid * 8;
    unsigned long long bo = g_bsum[b];
#pragma unroll
    for (int k = 0; k < 8; k++) {
        int j = base + k;
        if (j >= NP) continue;
        int r = j / N_NODES, d = j - r * N_NODES;
        int c = g_cnt[d * N_REL + r];
        if (c > 0) {
            unsigned long long f = g_scanv[j] + bo;
            int off = (int)(f & 0xffffffffull);
            int a = (int)(f >> 32);
            g_aggDst[a] = d;
            g_aggStart[a] = off;
            g_aggCnt[a] = c;
            g_curE[d * N_REL + r] = off;
        }
    }
}

__global__ void k_escatter(const int* __restrict__ ei, const int* __restrict__ et) {
    int e = blockIdx.x * blockDim.x + threadIdx.x;
    if (e < N_EDGES) {
        int d = ei[e], r = et[e], s = ei[N_EDGES + e];
        int pos = atomicAdd(&g_curE[d * N_REL + r], 1);
        g_srcS[pos] = s;
    }
}

// pre-swizzle W[l][r] -> bf16 blocks matching smem layout (one block per (l,r))
__global__ void k_wcvt(const float* __restrict__ W) {
    int blk = blockIdx.x;
    int tid = threadIdx.x;
    int row = tid >> 1, h = tid & 1;
    const float* src = W + ((size_t)blk * HIDDEN + row) * HIDDEN + h * 64;
    char* dst = g_wbf + (size_t)blk * 32768;
#pragma unroll
    for (int i = 0; i < 8; i++) {
        float4 x = *(const float4*)(src + i * 8);
        float4 y = *(const float4*)(src + i * 8 + 4);
        *(uint4*)(dst + swz(row, h * 128 + i * 16)) = cvt8(x, y, 0);
    }
}

// fused: fp32->bf16 convert (relu) of layer input  +  bias init of layer output
__global__ void k_prep(const float* __restrict__ in, int relu,
                       const float* __restrict__ bias, float* __restrict__ out) {
    __shared__ float sb[N_REL * HIDDEN];
    int tid = threadIdx.x, wid = tid >> 5, lid = tid & 31;
    for (int i = tid; i < N_REL * HIDDEN; i += blockDim.x) sb[i] = bias[i];
    __syncthreads();

    int stride = gridDim.x * blockDim.x;
    for (int i = blockIdx.x * blockDim.x + tid; i < N_NODES * HIDDEN / 8; i += stride) {
        const float4* s = (const float4*)(in + (size_t)i * 8);
        float4 x = s[0], y = s[1];
        *(uint4*)(g_inb + (size_t)i * 8) = cvt8(x, y, relu);
    }

    int warps = gridDim.x * (blockDim.x >> 5);
    for (int node = blockIdx.x * (blockDim.x >> 5) + wid; node < N_NODES; node += warps) {
        const int* c = &g_cnt[node * N_REL];
        float4 acc = make_float4(0.f, 0.f, 0.f, 0.f);
#pragma unroll
        for (int r = 0; r < N_REL; r++) {
            float cf = (float)__ldg(&c[r]);
            float4 b = *(const float4*)&sb[r * HIDDEN + lid * 4];
            acc.x += cf * b.x; acc.y += cf * b.y;
            acc.z += cf * b.z; acc.w += cf * b.w;
        }
        *(float4*)&out[(size_t)node * HIDDEN + lid * 4] = acc;
    }
}

// aggregate: agg[a] = bf16( sum_{edges of group a} fp32(inb[src]) )
__global__ void __launch_bounds__(256) k_agg() {
    int total = g_aggTotal;
    int wid = threadIdx.x >> 5, lid = threadIdx.x & 31;
    int gw = blockIdx.x * 8 + wid, nw = gridDim.x * 8;
    for (int a = gw; a < total; a += nw) {
        int st = g_aggStart[a], c = g_aggCnt[a];
        float a0 = 0.f, a1 = 0.f, a2 = 0.f, a3 = 0.f;
        for (int i = 0; i < c; i++) {
            int s = g_srcS[st + i];
            uint2 u = *(const uint2*)(g_inb + (size_t)s * HIDDEN + lid * 4);
            __nv_bfloat162 b0 = *(__nv_bfloat162*)&u.x;
            __nv_bfloat162 b1 = *(__nv_bfloat162*)&u.y;
            float2 f0 = __bfloat1622float2(b0);
            float2 f1 = __bfloat1622float2(b1);
            a0 += f0.x; a1 += f0.y; a2 += f1.x; a3 += f1.y;
        }
        __nv_bfloat162 o0 = __floats2bfloat162_rn(a0, a1);
        __nv_bfloat162 o1 = __floats2bfloat162_rn(a2, a3);
        uint2 o;
        o.x = *(unsigned*)&o0; o.y = *(unsigned*)&o1;
        *(uint2*)(g_agg + (size_t)a * HIDDEN + lid * 4) = o;
    }
}

// ---------------- fused (sequential A load) + mma.sync + scatter ----------------
static constexpr int SM_W = 0;       // 32 KB: W_r bf16 swizzled
static constexpr int SM_A0 = 32768;  // 32 KB: A tile buf 0
static constexpr int SM_A1 = 65536;  // 32 KB: A tile buf 1
static constexpr int SMEM_DYN = 98304 + 512;

__device__ __forceinline__ void issue_gather(const char* aggb, uint32_t sbA,
                                             int tStart, int cnt, int row, int h) {
    int sz = (row < cnt) ? 16 : 0;
    int ar = min(tStart + row, NP - 1);            // clamp (sz=0 rows)
    const char* src = aggb + (size_t)ar * 256 + h * 128;
#pragma unroll
    for (int i = 0; i < 8; i++) {
        uint32_t dst = sbA + swz(row, h * 128 + i * 16);
        asm volatile("cp.async.cg.shared.global [%0], [%1], 16, %2;"
                     :: "r"(dst), "l"(src + i * 16), "r"(sz));
    }
}

__global__ void __launch_bounds__(256, 2)
k_fused(const char* __restrict__ wswz, float* __restrict__ out) {
    extern __shared__ char smraw[];
    uint32_t sbRaw = smem_u32(smraw);
    uint32_t sb = (sbRaw + 255) & ~255u;
    int tid = threadIdx.x, wid = tid >> 5, lid = tid & 31;

    const char* aggb = (const char*)g_agg;

    int T = g_numTiles;
    int per = (T + gridDim.x - 1) / gridDim.x;
    int t0 = blockIdx.x * per;
    int t1 = min(T, t0 + per);
    if (t0 >= t1) return;

    int row = tid >> 1, h = tid & 1;   // gather: 2 threads per row
    int m0 = (wid & 3) * 32;           // warp's row slab
    int n0 = (wid >> 2) * 64;          // warp's col slab
    int q = lid & 3;

    issue_gather(aggb, sb + SM_A0, g_tileStart[t0], g_tileCnt[t0], row, h);
    asm volatile("cp.async.commit_group;" ::: "memory");

    int curRel = -1, p = 0;
    for (int t = t0; t < t1; t++) {
        asm volatile("cp.async.wait_group 0;" ::: "memory");
        __syncthreads();

        int r = g_tileRel[t];
        if (r != curRel) {
            const char* wr = wswz + (size_t)r * 32768;
#pragma unroll
            for (int i = 0; i < 8; i++) {
                uint32_t dst = sb + SM_W + tid * 16 + i * 4096;
                asm volatile("cp.async.cg.shared.global [%0], [%1], 16;"
                             :: "r"(dst), "l"(wr + tid * 16 + i * 4096));
            }
            asm volatile("cp.async.commit_group;" ::: "memory");
            asm volatile("cp.async.wait_group 0;" ::: "memory");
            __syncthreads();
            curRel = r;
        }

        if (t + 1 < t1) {
            issue_gather(aggb, sb + (p ? SM_A0 : SM_A1),
                         g_tileStart[t + 1], g_tileCnt[t + 1], row, h);
            asm volatile("cp.async.commit_group;" ::: "memory");
        }

        int start = g_tileStart[t], cnt = g_tileCnt[t];
        uint32_t sbA = sb + (p ? SM_A1 : SM_A0);

        // ---- 32x64x128 per warp via m16n8k16 ----
        float c[2][8][4];
#pragma unroll
        for (int mh = 0; mh < 2; mh++)
#pragma unroll
            for (int nn = 0; nn < 8; nn++)
#pragma unroll
                for (int j = 0; j < 4; j++) c[mh][nn][j] = 0.f;

#pragma unroll
        for (int kk = 0; kk < 8; kk++) {
            uint32_t a[2][4];
#pragma unroll
            for (int mh = 0; mh < 2; mh++) {
                uint32_t aaddr = sbA + swz(m0 + mh * 16 + (lid & 15), kk * 32 + (lid >> 4) * 16);
                asm volatile("ldmatrix.sync.aligned.m8n8.x4.shared.b16 {%0,%1,%2,%3}, [%4];"
                             : "=r"(a[mh][0]), "=r"(a[mh][1]), "=r"(a[mh][2]), "=r"(a[mh][3])
                             : "r"(aaddr));
            }
#pragma unroll
            for (int nn2 = 0; nn2 < 4; nn2++) {
                uint32_t b0, b1, b2, b3;
                uint32_t baddr = sb + SM_W +
                    swz(kk * 16 + (lid & 15), n0 * 2 + nn2 * 32 + (lid >> 4) * 16);
                asm volatile("ldmatrix.sync.aligned.m8n8.x4.trans.shared.b16 {%0,%1,%2,%3}, [%4];"
                             : "=r"(b0), "=r"(b1), "=r"(b2), "=r"(b3) : "r"(baddr));
#pragma unroll
                for (int mh = 0; mh < 2; mh++) {
                    asm volatile("mma.sync.aligned.m16n8k16.row.col.f32.bf16.bf16.f32 "
                                 "{%0,%1,%2,%3}, {%4,%5,%6,%7}, {%8,%9}, {%0,%1,%2,%3};"
                                 : "+f"(c[mh][2 * nn2][0]), "+f"(c[mh][2 * nn2][1]),
                                   "+f"(c[mh][2 * nn2][2]), "+f"(c[mh][2 * nn2][3])
                                 : "r"(a[mh][0]), "r"(a[mh][1]), "r"(a[mh][2]), "r"(a[mh][3]),
                                   "r"(b0), "r"(b1));
                    asm volatile("mma.sync.aligned.m16n8k16.row.col.f32.bf16.bf16.f32 "
                                 "{%0,%1,%2,%3}, {%4,%5,%6,%7}, {%8,%9}, {%0,%1,%2,%3};"
                                 : "+f"(c[mh][2 * nn2 + 1][0]), "+f"(c[mh][2 * nn2 + 1][1]),
                                   "+f"(c[mh][2 * nn2 + 1][2]), "+f"(c[mh][2 * nn2 + 1][3])
                                 : "r"(a[mh][0]), "r"(a[mh][1]), "r"(a[mh][2]), "r"(a[mh][3]),
                                   "r"(b2), "r"(b3));
                }
            }
        }

        // ---- scatter: shuffle-pack quads into red.global.add.v4 ----
        bool even = (q & 1) == 0;
#pragma unroll
        for (int mh = 0; mh < 2; mh++) {
            int r0 = m0 + mh * 16 + (lid >> 2);
            int r1 = r0 + 8;
            int myrow = even ? r0 : r1;
            bool act = myrow < cnt;
            float* pbase = act
                ? out + (size_t)g_aggDst[start + myrow] * HIDDEN + n0 + (q >> 1) * 4
                : nullptr;
#pragma unroll
            for (int nn = 0; nn < 8; nn++) {
                float s0 = even ? c[mh][nn][2] : c[mh][nn][0];
                float s1 = even ? c[mh][nn][3] : c[mh][nn][1];
                float p0 = __shfl_xor_sync(0xffffffffu, s0, 1);
                float p1 = __shfl_xor_sync(0xffffffffu, s1, 1);
                float v0, v1, v2, v3;
                if (even) { v0 = c[mh][nn][0]; v1 = c[mh][nn][1]; v2 = p0; v3 = p1; }
                else      { v0 = p0; v1 = p1; v2 = c[mh][nn][2]; v3 = c[mh][nn][3]; }
                if (act)
                    asm volatile("red.global.add.v4.f32 [%0], {%1,%2,%3,%4};"
                                 :: "l"(pbase + nn * 8),
                                    "f"(v0), "f"(v1), "f"(v2), "f"(v3) : "memory");
            }
        }
        p ^= 1;
    }
}

// ---------------- launch ----------------
extern "C" void kernel_launch(void* const* d_in, const int* in_sizes, int n_in,
                              void* d_out, int out_size) {
    const int* ei = (const int*)d_in[0];     // [2, E]: row0 = dest, row1 = src
    const int* et = (const int*)d_in[1];     // [E]
    const float* emb = (const float*)d_in[2];// [N, H]
    const float* Wt = (const float*)d_in[3]; // [L, R, H, H]
    const float* Bi = (const float*)d_in[4]; // [L, R, H]
    float* out = (float*)d_out;              // [N, H]
    (void)in_sizes; (void)n_in; (void)out_size;

    void* pc; cudaGetSymbolAddress(&pc, g_cnt);
    void* pbuf; cudaGetSymbolAddress(&pbuf, g_buf);
    void* pwb; cudaGetSymbolAddress(&pwb, g_wbf);
    float* bufA = (float*)pbuf;
    float* bufB = bufA + (size_t)N_NODES * HIDDEN;
    const char* wb = (const char*)pwb;

    cudaMemsetAsync(pc, 0, (size_t)NP * sizeof(int));

    int eb = (N_EDGES + 255) / 256;
    k_hist<<<eb, 256>>>(ei, et);
    k_scan1<<<SCAN_NBLK, 512>>>();
    k_scan2tiles<<<1, 512>>>();
    k_scan3<<<SCAN_NBLK, 512>>>();
    k_escatter<<<eb, 256>>>(ei, et);
    k_wcvt<<<N_LAYERS * N_REL, 256>>>(Wt);

    cudaFuncSetAttribute(k_fused, cudaFuncAttributeMaxDynamicSharedMemorySize, SMEM_DYN);

    const float* lin[N_LAYERS] = {emb, bufA, bufB};
    float* lout[N_LAYERS] = {bufA, bufB, out};
    for (int l = 0; l < N_LAYERS; l++) {
        k_prep<<<256, 256>>>(lin[l], l > 0 ? 1 : 0,
                             Bi + (size_t)l * N_REL * HIDDEN, lout[l]);
        k_agg<<<1024, 256>>>();
        k_fused<<<296, 256, SMEM_DYN>>>(wb + (size_t)l * N_REL * 32768, lout[l]);
    }
}

// round 12
// speedup vs baseline: 1.1310x; 1.1310x over previous
#include <cuda_runtime.h>
#include <cuda_bf16.h>
#include <cstdint>

#define N_NODES 50000
#define HIDDEN 128
#define N_REL 9
#define N_LAYERS 3
#define N_EDGES 600000
#define TILE_M 128
#define MAX_TILES 4800

// ---------------- device scratch (no allocations allowed) ----------------
__device__ float g_buf[2][N_NODES * HIDDEN];          // layer ping-pong fp32
__device__ __nv_bfloat16 g_inb[N_NODES * HIDDEN];     // bf16 layer input
__device__ char g_wbf[N_LAYERS * N_REL * 32768];      // pre-swizzled bf16 weights
__device__ int g_srcS[N_EDGES];
__device__ int g_dstS[N_EDGES];
__device__ int g_cntAll[N_NODES * N_REL + N_REL];     // [cnt | relCount] one memset
__device__ int g_relCursor[N_REL];
__device__ int g_tileRel[MAX_TILES];
__device__ int g_tileStart[MAX_TILES];
__device__ int g_tileCnt[MAX_TILES];
__device__ int g_numTiles;

// ---------------- helpers ----------------
__device__ __forceinline__ uint32_t smem_u32(const void* p) {
    uint32_t a;
    asm("{ .reg .u64 t; cvta.to.shared.u64 t, %1; cvt.u32.u64 %0, t; }" : "=r"(a) : "l"(p));
    return a;
}

// 256-byte rows, XOR-swizzle 16B group index with (row & 7): conflict-free ldmatrix
__device__ __forceinline__ uint32_t swz(int row, int colByte) {
    return (uint32_t)(row * 256 + (colByte ^ ((row & 7) << 4)));
}

__device__ __forceinline__ uint4 cvt8(float4 x, float4 y, int relu) {
    if (relu) {
        x.x = fmaxf(x.x, 0.f); x.y = fmaxf(x.y, 0.f);
        x.z = fmaxf(x.z, 0.f); x.w = fmaxf(x.w, 0.f);
        y.x = fmaxf(y.x, 0.f); y.y = fmaxf(y.y, 0.f);
        y.z = fmaxf(y.z, 0.f); y.w = fmaxf(y.w, 0.f);
    }
    __nv_bfloat162 b0 = __floats2bfloat162_rn(x.x, x.y);
    __nv_bfloat162 b1 = __floats2bfloat162_rn(x.z, x.w);
    __nv_bfloat162 b2 = __floats2bfloat162_rn(y.x, y.y);
    __nv_bfloat162 b3 = __floats2bfloat162_rn(y.z, y.w);
    uint4 u;
    u.x = *(unsigned*)&b0; u.y = *(unsigned*)&b1;
    u.z = *(unsigned*)&b2; u.w = *(unsigned*)&b3;
    return u;
}

// ---------------- pre-pass kernels ----------------
__global__ void k_hist(const int* __restrict__ ei, const int* __restrict__ et) {
    __shared__ int sh[N_REL];
    int tid = threadIdx.x;
    if (tid < N_REL) sh[tid] = 0;
    __syncthreads();
    int e = blockIdx.x * blockDim.x + tid;
    if (e < N_EDGES) {
        int t = et[e];
        int d = ei[e];
        atomicAdd(&g_cntAll[d * N_REL + t], 1);
        atomicAdd(&sh[t], 1);
    }
    __syncthreads();
    if (tid < N_REL && sh[tid]) atomicAdd(&g_cntAll[N_NODES * N_REL + tid], sh[tid]);
}

__global__ void k_tiles() {
    __shared__ int offs[N_REL + 1], toffs[N_REL + 1];
    const int* relCount = &g_cntAll[N_NODES * N_REL];
    if (threadIdx.x == 0) {
        int o = 0, to = 0;
        for (int r = 0; r < N_REL; r++) {
            offs[r] = o; toffs[r] = to;
            g_relCursor[r] = o;
            int c = relCount[r];
            o += c;
            to += (c + TILE_M - 1) / TILE_M;
        }
        offs[N_REL] = o; toffs[N_REL] = to;
        g_numTiles = to;
    }
    __syncthreads();
    for (int r = 0; r < N_REL; r++) {
        int c = relCount[r];
        int nt = (c + TILE_M - 1) / TILE_M;
        for (int i = threadIdx.x; i < nt; i += blockDim.x) {
            int t = toffs[r] + i;
            g_tileRel[t] = r;
            g_tileStart[t] = offs[r] + i * TILE_M;
            g_tileCnt[t] = min(TILE_M, c - i * TILE_M);
        }
    }
}

__global__ void k_scatter(const int* __restrict__ ei, const int* __restrict__ et) {
    __shared__ int sCnt[N_REL], sBase[N_REL];
    int tid = threadIdx.x;
    if (tid < N_REL) sCnt[tid] = 0;
    __syncthreads();
    int e = blockIdx.x * blockDim.x + tid;
    int t = 0, loc = 0, s = 0, d = 0;
    bool v = (e < N_EDGES);
    if (v) {
        t = et[e]; d = ei[e]; s = ei[N_EDGES + e];
        loc = atomicAdd(&sCnt[t], 1);
    }
    __syncthreads();
    if (tid < N_REL && sCnt[tid] > 0) sBase[tid] = atomicAdd(&g_relCursor[tid], sCnt[tid]);
    __syncthreads();
    if (v) {
        int pos = sBase[t] + loc;
        g_srcS[pos] = s;
        g_dstS[pos] = d;
    }
}

// fused prep: bf16 convert (relu) + bias init; blocks >= nprep pre-swizzle weights
__global__ void k_prep(const float* __restrict__ in, int relu,
                       const float* __restrict__ bias, float* __restrict__ out,
                       const float* __restrict__ W, int nprep) {
    int tid = threadIdx.x;
    if ((int)blockIdx.x >= nprep) {
        // weight conversion duty: one logical block per (l,r)
        int blk = blockIdx.x - nprep;
        int row = tid >> 1, h = tid & 1;
        const float* src = W + ((size_t)blk * HIDDEN + row) * HIDDEN + h * 64;
        char* dst = g_wbf + (size_t)blk * 32768;
#pragma unroll
        for (int i = 0; i < 8; i++) {
            float4 x = *(const float4*)(src + i * 8);
            float4 y = *(const float4*)(src + i * 8 + 4);
            *(uint4*)(dst + swz(row, h * 128 + i * 16)) = cvt8(x, y, 0);
        }
        return;
    }

    __shared__ float sb[N_REL * HIDDEN];
    int wid = tid >> 5, lid = tid & 31;
    for (int i = tid; i < N_REL * HIDDEN; i += blockDim.x) sb[i] = bias[i];
    __syncthreads();

    int stride = nprep * blockDim.x;
    for (int i = blockIdx.x * blockDim.x + tid; i < N_NODES * HIDDEN / 8; i += stride) {
        const float4* s = (const float4*)(in + (size_t)i * 8);
        float4 x = s[0], y = s[1];
        *(uint4*)(g_inb + (size_t)i * 8) = cvt8(x, y, relu);
    }

    int warps = nprep * (blockDim.x >> 5);
    for (int node = blockIdx.x * (blockDim.x >> 5) + wid; node < N_NODES; node += warps) {
        const int* c = &g_cntAll[node * N_REL];
        float4 acc = make_float4(0.f, 0.f, 0.f, 0.f);
#pragma unroll
        for (int r = 0; r < N_REL; r++) {
            float cf = (float)__ldg(&c[r]);
            float4 b = *(const float4*)&sb[r * HIDDEN + lid * 4];
            acc.x += cf * b.x; acc.y += cf * b.y;
            acc.z += cf * b.z; acc.w += cf * b.w;
        }
        *(float4*)&out[(size_t)node * HIDDEN + lid * 4] = acc;
    }
}

// ---------------- fused gather + mma.sync + scatter (cp.async pipelined) -------
static constexpr int SM_W = 0;       // 32 KB: W_r bf16 swizzled
static constexpr int SM_A0 = 32768;  // 32 KB: A tile buf 0
static constexpr int SM_A1 = 65536;  // 32 KB: A tile buf 1
static constexpr int SMEM_DYN = 98304 + 512;

__device__ __forceinline__ void issue_gather(const char* inb, uint32_t sbA,
                                             int start, int cnt, int row, int h) {
    int sz = (row < cnt) ? 16 : 0;
    int node = (row < cnt) ? g_srcS[start + row] : 0;
    const char* src = inb + (size_t)node * 256 + h * 128;
#pragma unroll
    for (int i = 0; i < 8; i++) {
        uint32_t dst = sbA + swz(row, h * 128 + i * 16);
        asm volatile("cp.async.cg.shared.global [%0], [%1], 16, %2;"
                     :: "r"(dst), "l"(src + i * 16), "r"(sz));
    }
}

__global__ void __launch_bounds__(256, 2)
k_fused(const char* __restrict__ wswz, float* __restrict__ out) {
    extern __shared__ char smraw[];
    uint32_t sbRaw = smem_u32(smraw);
    uint32_t sb = (sbRaw + 255) & ~255u;
    int tid = threadIdx.x, wid = tid >> 5, lid = tid & 31;

    const char* inb = (const char*)g_inb;

    int T = g_numTiles;
    int per = (T + gridDim.x - 1) / gridDim.x;
    int t0 = blockIdx.x * per;
    int t1 = min(T, t0 + per);
    if (t0 >= t1) return;

    int row = tid >> 1, h = tid & 1;   // gather assignment: 2 threads per row
    int m0 = (wid & 3) * 32;           // warp's row slab
    int n0 = (wid >> 2) * 64;          // warp's col slab
    int q = lid & 3;

    issue_gather(inb, sb + SM_A0, g_tileStart[t0], g_tileCnt[t0], row, h);
    asm volatile("cp.async.commit_group;" ::: "memory");

    int curRel = -1, p = 0;
    for (int t = t0; t < t1; t++) {
        asm volatile("cp.async.wait_group 0;" ::: "memory");
        __syncthreads();

        int r = g_tileRel[t];
        if (r != curRel) {
            const char* wr = wswz + (size_t)r * 32768;
#pragma unroll
            for (int i = 0; i < 8; i++) {
                uint32_t dst = sb + SM_W + tid * 16 + i * 4096;
                asm volatile("cp.async.cg.shared.global [%0], [%1], 16;"
                             :: "r"(dst), "l"(wr + tid * 16 + i * 4096));
            }
            asm volatile("cp.async.commit_group;" ::: "memory");
            asm volatile("cp.async.wait_group 0;" ::: "memory");
            __syncthreads();
            curRel = r;
        }

        if (t + 1 < t1) {
            issue_gather(inb, sb + (p ? SM_A0 : SM_A1),
                         g_tileStart[t + 1], g_tileCnt[t + 1], row, h);
            asm volatile("cp.async.commit_group;" ::: "memory");
        }

        int start = g_tileStart[t], cnt = g_tileCnt[t];
        uint32_t sbA = sb + (p ? SM_A1 : SM_A0);

        // ---- 32x64x128 per warp via m16n8k16 ----
        float c[2][8][4];
#pragma unroll
        for (int mh = 0; mh < 2; mh++)
#pragma unroll
            for (int nn = 0; nn < 8; nn++)
#pragma unroll
                for (int j = 0; j < 4; j++) c[mh][nn][j] = 0.f;

#pragma unroll
        for (int kk = 0; kk < 8; kk++) {
            uint32_t a[2][4];
#pragma unroll
            for (int mh = 0; mh < 2; mh++) {
                uint32_t aaddr = sbA + swz(m0 + mh * 16 + (lid & 15), kk * 32 + (lid >> 4) * 16);
                asm volatile("ldmatrix.sync.aligned.m8n8.x4.shared.b16 {%0,%1,%2,%3}, [%4];"
                             : "=r"(a[mh][0]), "=r"(a[mh][1]), "=r"(a[mh][2]), "=r"(a[mh][3])
                             : "r"(aaddr));
            }
#pragma unroll
            for (int nn2 = 0; nn2 < 4; nn2++) {
                uint32_t b0, b1, b2, b3;
                uint32_t baddr = sb + SM_W +
                    swz(kk * 16 + (lid & 15), n0 * 2 + nn2 * 32 + (lid >> 4) * 16);
                asm volatile("ldmatrix.sync.aligned.m8n8.x4.trans.shared.b16 {%0,%1,%2,%3}, [%4];"
                             : "=r"(b0), "=r"(b1), "=r"(b2), "=r"(b3) : "r"(baddr));
#pragma unroll
                for (int mh = 0; mh < 2; mh++) {
                    asm volatile("mma.sync.aligned.m16n8k16.row.col.f32.bf16.bf16.f32 "
                                 "{%0,%1,%2,%3}, {%4,%5,%6,%7}, {%8,%9}, {%0,%1,%2,%3};"
                                 : "+f"(c[mh][2 * nn2][0]), "+f"(c[mh][2 * nn2][1]),
                                   "+f"(c[mh][2 * nn2][2]), "+f"(c[mh][2 * nn2][3])
                                 : "r"(a[mh][0]), "r"(a[mh][1]), "r"(a[mh][2]), "r"(a[mh][3]),
                                   "r"(b0), "r"(b1));
                    asm volatile("mma.sync.aligned.m16n8k16.row.col.f32.bf16.bf16.f32 "
                                 "{%0,%1,%2,%3}, {%4,%5,%6,%7}, {%8,%9}, {%0,%1,%2,%3};"
                                 : "+f"(c[mh][2 * nn2 + 1][0]), "+f"(c[mh][2 * nn2 + 1][1]),
                                   "+f"(c[mh][2 * nn2 + 1][2]), "+f"(c[mh][2 * nn2 + 1][3])
                                 : "r"(a[mh][0]), "r"(a[mh][1]), "r"(a[mh][2]), "r"(a[mh][3]),
                                   "r"(b2), "r"(b3));
                }
            }
        }

        // ---- scatter: shuffle-pack quads into red.global.add.v4 ----
        bool even = (q & 1) == 0;
#pragma unroll
        for (int mh = 0; mh < 2; mh++) {
            int r0 = m0 + mh * 16 + (lid >> 2);
            int r1 = r0 + 8;
            int myrow = even ? r0 : r1;
            bool act = myrow < cnt;
            float* pbase = act
                ? out + (size_t)g_dstS[start + myrow] * HIDDEN + n0 + (q >> 1) * 4
                : nullptr;
#pragma unroll
            for (int nn = 0; nn < 8; nn++) {
                float s0 = even ? c[mh][nn][2] : c[mh][nn][0];
                float s1 = even ? c[mh][nn][3] : c[mh][nn][1];
                float p0 = __shfl_xor_sync(0xffffffffu, s0, 1);
                float p1 = __shfl_xor_sync(0xffffffffu, s1, 1);
                float v0, v1, v2, v3;
                if (even) { v0 = c[mh][nn][0]; v1 = c[mh][nn][1]; v2 = p0; v3 = p1; }
                else      { v0 = p0; v1 = p1; v2 = c[mh][nn][2]; v3 = c[mh][nn][3]; }
                if (act)
                    asm volatile("red.global.add.v4.f32 [%0], {%1,%2,%3,%4};"
                                 :: "l"(pbase + nn * 8),
                                    "f"(v0), "f"(v1), "f"(v2), "f"(v3) : "memory");
            }
        }
        p ^= 1;
    }
}

// ---------------- launch ----------------
extern "C" void kernel_launch(void* const* d_in, const int* in_sizes, int n_in,
                              void* d_out, int out_size) {
    const int* ei = (const int*)d_in[0];     // [2, E]: row0 = dest, row1 = src
    const int* et = (const int*)d_in[1];     // [E]
    const float* emb = (const float*)d_in[2];// [N, H]
    const float* Wt = (const float*)d_in[3]; // [L, R, H, H]
    const float* Bi = (const float*)d_in[4]; // [L, R, H]
    float* out = (float*)d_out;              // [N, H]
    (void)in_sizes; (void)n_in; (void)out_size;

    void* pc; cudaGetSymbolAddress(&pc, g_cntAll);
    void* pbuf; cudaGetSymbolAddress(&pbuf, g_buf);
    void* pwb; cudaGetSymbolAddress(&pwb, g_wbf);
    float* bufA = (float*)pbuf;
    float* bufB = bufA + (size_t)N_NODES * HIDDEN;
    const char* wb = (const char*)pwb;

    // launch order fixed so ncu (-s 5 -c 1) captures the first k_fused:
    // 0: memset  1: k_hist  2: k_tiles  3: k_scatter  4: k_prep(l0+wcvt)  5: k_fused(l0)
    cudaMemsetAsync(pc, 0, ((size_t)N_NODES * N_REL + N_REL) * sizeof(int));

    int eb = (N_EDGES + 255) / 256;
    k_hist<<<eb, 256>>>(ei, et);
    k_tiles<<<1, 256>>>();
    k_scatter<<<eb, 256>>>(ei, et);

    cudaFuncSetAttribute(k_fused, cudaFuncAttributeMaxDynamicSharedMemorySize, SMEM_DYN);

    const float* lin[N_LAYERS] = {emb, bufA, bufB};
    float* lout[N_LAYERS] = {bufA, bufB, out};
    for (int l = 0; l < N_LAYERS; l++) {
        int grid = (l == 0) ? 256 + N_LAYERS * N_REL : 256;   // layer 0 also converts weights
        k_prep<<<grid, 256>>>(lin[l], l > 0 ? 1 : 0,
                              Bi + (size_t)l * N_REL * HIDDEN, lout[l], Wt, 256);
        k_fused<<<296, 256, SMEM_DYN>>>(wb + (size_t)l * N_REL * 32768, lout[l]);
    }
}

// round 14
// speedup vs baseline: 1.1427x; 1.0104x over previous
#include <cuda_runtime.h>
#include <cuda_bf16.h>
#include <cstdint>

#define N_NODES 50000
#define HIDDEN 128
#define N_REL 9
#define N_LAYERS 3
#define N_EDGES 600000
#define TILE_M 128
#define MAX_TILES 4800
#define NP (N_NODES * N_REL)

// ---------------- device scratch (no allocations allowed) ----------------
__device__ float g_buf[2][N_NODES * HIDDEN];          // layer ping-pong fp32
__device__ __nv_bfloat16 g_inb[N_NODES * HIDDEN];     // bf16 layer input
__device__ char g_wbf[N_LAYERS * N_REL * 32768];      // pre-swizzled bf16 weights
__device__ int g_srcS[N_EDGES];
__device__ int g_dstS[N_EDGES];
// [0,NP): per-(node,rel) counts | [NP,NP+9): relCount | [NP+9,NP+18): scatter cursor
__device__ int g_cntAll[NP + 2 * N_REL];
__device__ int g_tileRel[MAX_TILES];
__device__ int g_tileStart[MAX_TILES];
__device__ int g_tileCnt[MAX_TILES];
__device__ int g_numTiles;

// ---------------- helpers ----------------
__device__ __forceinline__ uint32_t smem_u32(const void* p) {
    uint32_t a;
    asm("{ .reg .u64 t; cvta.to.shared.u64 t, %1; cvt.u32.u64 %0, t; }" : "=r"(a) : "l"(p));
    return a;
}

// 256-byte rows, XOR-swizzle 16B group index with (row & 7): conflict-free ldmatrix
__device__ __forceinline__ uint32_t swz(int row, int colByte) {
    return (uint32_t)(row * 256 + (colByte ^ ((row & 7) << 4)));
}

__device__ __forceinline__ uint4 cvt8(float4 x, float4 y, int relu) {
    if (relu) {
        x.x = fmaxf(x.x, 0.f); x.y = fmaxf(x.y, 0.f);
        x.z = fmaxf(x.z, 0.f); x.w = fmaxf(x.w, 0.f);
        y.x = fmaxf(y.x, 0.f); y.y = fmaxf(y.y, 0.f);
        y.z = fmaxf(y.z, 0.f); y.w = fmaxf(y.w, 0.f);
    }
    __nv_bfloat162 b0 = __floats2bfloat162_rn(x.x, x.y);
    __nv_bfloat162 b1 = __floats2bfloat162_rn(x.z, x.w);
    __nv_bfloat162 b2 = __floats2bfloat162_rn(y.x, y.y);
    __nv_bfloat162 b3 = __floats2bfloat162_rn(y.z, y.w);
    uint4 u;
    u.x = *(unsigned*)&b0; u.y = *(unsigned*)&b1;
    u.z = *(unsigned*)&b2; u.w = *(unsigned*)&b3;
    return u;
}

// ---------------- pre-pass kernels ----------------
__global__ void k_hist(const int* __restrict__ ei, const int* __restrict__ et) {
    __shared__ int sh[N_REL];
    int tid = threadIdx.x;
    if (tid < N_REL) sh[tid] = 0;
    __syncthreads();
    int e = blockIdx.x * blockDim.x + tid;
    if (e < N_EDGES) {
        int t = et[e];
        int d = ei[e];
        atomicAdd(&g_cntAll[d * N_REL + t], 1);
        atomicAdd(&sh[t], 1);
    }
    __syncthreads();
    if (tid < N_REL && sh[tid]) atomicAdd(&g_cntAll[NP + tid], sh[tid]);
}

// counting-sort scatter; per-block computes rel offsets from relCount prefix
__global__ void k_scatter(const int* __restrict__ ei, const int* __restrict__ et) {
    __shared__ int sCnt[N_REL], sBase[N_REL], sOff[N_REL];
    int tid = threadIdx.x;
    if (tid < N_REL) sCnt[tid] = 0;
    if (tid == 0) {
        int o = 0;
#pragma unroll
        for (int r = 0; r < N_REL; r++) { sOff[r] = o; o += g_cntAll[NP + r]; }
    }
    __syncthreads();
    int e = blockIdx.x * blockDim.x + tid;
    int t = 0, loc = 0, s = 0, d = 0;
    bool v = (e < N_EDGES);
    if (v) {
        t = et[e]; d = ei[e]; s = ei[N_EDGES + e];
        loc = atomicAdd(&sCnt[t], 1);
    }
    __syncthreads();
    if (tid < N_REL && sCnt[tid] > 0)
        sBase[tid] = sOff[tid] + atomicAdd(&g_cntAll[NP + N_REL + tid], sCnt[tid]);
    __syncthreads();
    if (v) {
        int pos = sBase[t] + loc;
        g_srcS[pos] = s;
        g_dstS[pos] = d;
    }
}

// fused prep: bf16 convert (relu) + bias init; extra blocks: weight swizzle + tiles
__global__ void k_prep(const float* __restrict__ in, int relu,
                       const float* __restrict__ bias, float* __restrict__ out,
                       const float* __restrict__ W, int nprep) {
    int tid = threadIdx.x;
    int xb = (int)blockIdx.x - nprep;
    if (xb >= 0) {
        if (xb < N_LAYERS * N_REL) {
            // weight conversion: one block per (l,r)
            int row = tid >> 1, h = tid & 1;
            const float* src = W + ((size_t)xb * HIDDEN + row) * HIDDEN + h * 64;
            char* dst = g_wbf + (size_t)xb * 32768;
#pragma unroll
            for (int i = 0; i < 8; i++) {
                float4 x = *(const float4*)(src + i * 8);
                float4 y = *(const float4*)(src + i * 8 + 4);
                *(uint4*)(dst + swz(row, h * 128 + i * 16)) = cvt8(x, y, 0);
            }
        } else {
            // tile-table construction (single block)
            __shared__ int offs[N_REL + 1], toffs[N_REL + 1];
            if (tid == 0) {
                int o = 0, to = 0;
                for (int r = 0; r < N_REL; r++) {
                    offs[r] = o; toffs[r] = to;
                    int c = g_cntAll[NP + r];
                    o += c;
                    to += (c + TILE_M - 1) / TILE_M;
                }
                offs[N_REL] = o; toffs[N_REL] = to;
                g_numTiles = to;
            }
            __syncthreads();
            for (int r = 0; r < N_REL; r++) {
                int c = offs[r + 1] - offs[r];
                int nt = (c + TILE_M - 1) / TILE_M;
                for (int i = tid; i < nt; i += blockDim.x) {
                    int t = toffs[r] + i;
                    g_tileRel[t] = r;
                    g_tileStart[t] = offs[r] + i * TILE_M;
                    g_tileCnt[t] = min(TILE_M, c - i * TILE_M);
                }
            }
        }
        return;
    }

    __shared__ float sb[N_REL * HIDDEN];
    int wid = tid >> 5, lid = tid & 31;
    for (int i = tid; i < N_REL * HIDDEN; i += blockDim.x) sb[i] = bias[i];
    __syncthreads();

    int stride = nprep * blockDim.x;
    for (int i = blockIdx.x * blockDim.x + tid; i < N_NODES * HIDDEN / 8; i += stride) {
        const float4* s = (const float4*)(in + (size_t)i * 8);
        float4 x = s[0], y = s[1];
        *(uint4*)(g_inb + (size_t)i * 8) = cvt8(x, y, relu);
    }

    int warps = nprep * (blockDim.x >> 5);
    for (int node = blockIdx.x * (blockDim.x >> 5) + wid; node < N_NODES; node += warps) {
        const int* c = &g_cntAll[node * N_REL];
        float4 acc = make_float4(0.f, 0.f, 0.f, 0.f);
#pragma unroll
        for (int r = 0; r < N_REL; r++) {
            float cf = (float)__ldg(&c[r]);
            float4 b = *(const float4*)&sb[r * HIDDEN + lid * 4];
            acc.x += cf * b.x; acc.y += cf * b.y;
            acc.z += cf * b.z; acc.w += cf * b.w;
        }
        *(float4*)&out[(size_t)node * HIDDEN + lid * 4] = acc;
    }
}

// ---------------- fused gather + mma.sync + scatter (cp.async pipelined) -------
static constexpr int SM_W = 0;       // 32 KB: W_r bf16 swizzled
static constexpr int SM_A0 = 32768;  // 32 KB: A tile buf 0
static constexpr int SM_A1 = 65536;  // 32 KB: A tile buf 1
static constexpr int SMEM_DYN = 98304 + 512;

__device__ __forceinline__ void issue_gather(const char* inb, uint32_t sbA,
                                             int start, int cnt, int row, int h) {
    int sz = (row < cnt) ? 16 : 0;
    int node = (row < cnt) ? g_srcS[start + row] : 0;
    const char* src = inb + (size_t)node * 256 + h * 128;
#pragma unroll
    for (int i = 0; i < 8; i++) {
        uint32_t dst = sbA + swz(row, h * 128 + i * 16);
        asm volatile("cp.async.cg.shared.global [%0], [%1], 16, %2;"
                     :: "r"(dst), "l"(src + i * 16), "r"(sz));
    }
}

__global__ void __launch_bounds__(256, 2)
k_fused(const char* __restrict__ wswz, float* __restrict__ out) {
    extern __shared__ char smraw[];
    uint32_t sbRaw = smem_u32(smraw);
    uint32_t sb = (sbRaw + 255) & ~255u;
    int tid = threadIdx.x, wid = tid >> 5, lid = tid & 31;

    const char* inb = (const char*)g_inb;

    int T = g_numTiles;
    int per = (T + gridDim.x - 1) / gridDim.x;
    int t0 = blockIdx.x * per;
    int t1 = min(T, t0 + per);
    if (t0 >= t1) return;

    int row = tid >> 1, h = tid & 1;   // gather assignment: 2 threads per row
    int m0 = (wid & 3) * 32;           // warp's row slab
    int n0 = (wid >> 2) * 64;          // warp's col slab
    int q = lid & 3;

    issue_gather(inb, sb + SM_A0, g_tileStart[t0], g_tileCnt[t0], row, h);
    asm volatile("cp.async.commit_group;" ::: "memory");

    int curRel = -1, p = 0;
    for (int t = t0; t < t1; t++) {
        asm volatile("cp.async.wait_group 0;" ::: "memory");
        __syncthreads();

        int r = g_tileRel[t];
        if (r != curRel) {
            const char* wr = wswz + (size_t)r * 32768;
#pragma unroll
            for (int i = 0; i < 8; i++) {
                uint32_t dst = sb + SM_W + tid * 16 + i * 4096;
                asm volatile("cp.async.cg.shared.global [%0], [%1], 16;"
                             :: "r"(dst), "l"(wr + tid * 16 + i * 4096));
            }
            asm volatile("cp.async.commit_group;" ::: "memory");
            asm volatile("cp.async.wait_group 0;" ::: "memory");
            __syncthreads();
            curRel = r;
        }

        if (t + 1 < t1) {
            issue_gather(inb, sb + (p ? SM_A0 : SM_A1),
                         g_tileStart[t + 1], g_tileCnt[t + 1], row, h);
            asm volatile("cp.async.commit_group;" ::: "memory");
        }

        int start = g_tileStart[t], cnt = g_tileCnt[t];
        uint32_t sbA = sb + (p ? SM_A1 : SM_A0);

        // ---- 32x64x128 per warp via m16n8k16 ----
        float c[2][8][4];
#pragma unroll
        for (int mh = 0; mh < 2; mh++)
#pragma unroll
            for (int nn = 0; nn < 8; nn++)
#pragma unroll
                for (int j = 0; j < 4; j++) c[mh][nn][j] = 0.f;

#pragma unroll
        for (int kk = 0; kk < 8; kk++) {
            uint32_t a[2][4];
#pragma unroll
            for (int mh = 0; mh < 2; mh++) {
                uint32_t aaddr = sbA + swz(m0 + mh * 16 + (lid & 15), kk * 32 + (lid >> 4) * 16);
                asm volatile("ldmatrix.sync.aligned.m8n8.x4.shared.b16 {%0,%1,%2,%3}, [%4];"
                             : "=r"(a[mh][0]), "=r"(a[mh][1]), "=r"(a[mh][2]), "=r"(a[mh][3])
                             : "r"(aaddr));
            }
#pragma unroll
            for (int nn2 = 0; nn2 < 4; nn2++) {
                uint32_t b0, b1, b2, b3;
                uint32_t baddr = sb + SM_W +
                    swz(kk * 16 + (lid & 15), n0 * 2 + nn2 * 32 + (lid >> 4) * 16);
                asm volatile("ldmatrix.sync.aligned.m8n8.x4.trans.shared.b16 {%0,%1,%2,%3}, [%4];"
                             : "=r"(b0), "=r"(b1), "=r"(b2), "=r"(b3) : "r"(baddr));
#pragma unroll
                for (int mh = 0; mh < 2; mh++) {
                    asm volatile("mma.sync.aligned.m16n8k16.row.col.f32.bf16.bf16.f32 "
                                 "{%0,%1,%2,%3}, {%4,%5,%6,%7}, {%8,%9}, {%0,%1,%2,%3};"
                                 : "+f"(c[mh][2 * nn2][0]), "+f"(c[mh][2 * nn2][1]),
                                   "+f"(c[mh][2 * nn2][2]), "+f"(c[mh][2 * nn2][3])
                                 : "r"(a[mh][0]), "r"(a[mh][1]), "r"(a[mh][2]), "r"(a[mh][3]),
                                   "r"(b0), "r"(b1));
                    asm volatile("mma.sync.aligned.m16n8k16.row.col.f32.bf16.bf16.f32 "
                                 "{%0,%1,%2,%3}, {%4,%5,%6,%7}, {%8,%9}, {%0,%1,%2,%3};"
                                 : "+f"(c[mh][2 * nn2 + 1][0]), "+f"(c[mh][2 * nn2 + 1][1]),
                                   "+f"(c[mh][2 * nn2 + 1][2]), "+f"(c[mh][2 * nn2 + 1][3])
                                 : "r"(a[mh][0]), "r"(a[mh][1]), "r"(a[mh][2]), "r"(a[mh][3]),
                                   "r"(b2), "r"(b3));
                }
            }
        }

        // ---- scatter: shuffle-pack quads into red.global.add.v4 ----
        bool even = (q & 1) == 0;
#pragma unroll
        for (int mh = 0; mh < 2; mh++) {
            int r0 = m0 + mh * 16 + (lid >> 2);
            int r1 = r0 + 8;
            int myrow = even ? r0 : r1;
            bool act = myrow < cnt;
            float* pbase = act
                ? out + (size_t)g_dstS[start + myrow] * HIDDEN + n0 + (q >> 1) * 4
                : nullptr;
#pragma unroll
            for (int nn = 0; nn < 8; nn++) {
                float s0 = even ? c[mh][nn][2] : c[mh][nn][0];
                float s1 = even ? c[mh][nn][3] : c[mh][nn][1];
                float p0 = __shfl_xor_sync(0xffffffffu, s0, 1);
                float p1 = __shfl_xor_sync(0xffffffffu, s1, 1);
                float v0, v1, v2, v3;
                if (even) { v0 = c[mh][nn][0]; v1 = c[mh][nn][1]; v2 = p0; v3 = p1; }
                else      { v0 = p0; v1 = p1; v2 = c[mh][nn][2]; v3 = c[mh][nn][3]; }
                if (act)
                    asm volatile("red.global.add.v4.f32 [%0], {%1,%2,%3,%4};"
                                 :: "l"(pbase + nn * 8),
                                    "f"(v0), "f"(v1), "f"(v2), "f"(v3) : "memory");
            }
        }
        p ^= 1;
    }
}

// ---------------- launch ----------------
extern "C" void kernel_launch(void* const* d_in, const int* in_sizes, int n_in,
                              void* d_out, int out_size) {
    const int* ei = (const int*)d_in[0];     // [2, E]: row0 = dest, row1 = src
    const int* et = (const int*)d_in[1];     // [E]
    const float* emb = (const float*)d_in[2];// [N, H]
    const float* Wt = (const float*)d_in[3]; // [L, R, H, H]
    const float* Bi = (const float*)d_in[4]; // [L, R, H]
    float* out = (float*)d_out;              // [N, H]
    (void)in_sizes; (void)n_in; (void)out_size;

    void* pc; cudaGetSymbolAddress(&pc, g_cntAll);
    void* pbuf; cudaGetSymbolAddress(&pbuf, g_buf);
    void* pwb; cudaGetSymbolAddress(&pwb, g_wbf);
    float* bufA = (float*)pbuf;
    float* bufB = bufA + (size_t)N_NODES * HIDDEN;
    const char* wb = (const char*)pwb;

    // stream: [harness fill], memset, hist, scatter, prep0, fused0 <- ncu -s 5 slot
    cudaMemsetAsync(pc, 0, ((size_t)NP + 2 * N_REL) * sizeof(int));

    int eb = (N_EDGES + 255) / 256;
    k_hist<<<eb, 256>>>(ei, et);
    k_scatter<<<eb, 256>>>(ei, et);

    cudaFuncSetAttribute(k_fused, cudaFuncAttributeMaxDynamicSharedMemorySize, SMEM_DYN);

    const int NPREP = 512;
    const float* lin[N_LAYERS] = {emb, bufA, bufB};
    float* lout[N_LAYERS] = {bufA, bufB, out};
    for (int l = 0; l < N_LAYERS; l++) {
        // layer 0 also converts weights (27 blocks) and builds the tile table (1 block)
        int grid = (l == 0) ? NPREP + N_LAYERS * N_REL + 1 : NPREP;
        k_prep<<<grid, 256>>>(lin[l], l > 0 ? 1 : 0,
                              Bi + (size_t)l * N_REL * HIDDEN, lout[l], Wt, NPREP);
        k_fused<<<296, 256, SMEM_DYN>>>(wb + (size_t)l * N_REL * 32768, lout[l]);
    }
}